// round 1
// baseline (speedup 1.0000x reference)
#include <cuda_runtime.h>
#include <math.h>

#define MM     12     // models
#define TSOL   64
#define NXY    256
#define NTIMES 50

// Scratch (no cudaMalloc allowed)
__device__ float g_wl[MM * NXY];
__device__ float g_wr[MM * NXY];
__device__ int   g_iy[MM * NXY];
__device__ int   g_tidx[NTIMES];

// Replicate jax linspace element: k*fl(delta) for k<n-1, exact stop at k=n-1.
__device__ __forceinline__ float ys_val(int k, float d01, float lys, float fac) {
    float lin = (k == NXY - 1) ? 1.0f : __fmul_rn((float)k, d01);
    return __fmul_rn(__fmul_rn(lin, lys), fac);
}

__global__ void setup_kernel(const float* __restrict__ params,
                             const float* __restrict__ Wq, const float* __restrict__ bq,
                             const float* __restrict__ Wk, const float* __restrict__ bk) {
    __shared__ float s_w[MM], s_lys[MM], s_fac[MM];
    int tid = threadIdx.x;

    if (tid == 0) {
        // target vector (python-double math folded to f32, matching jnp.array of py floats)
        const float t0 = 0.5f;                       // (75-30)/90
        const float t1 = (float)(0.001 / 0.0029);
        const float t2 = (float)(0.0001 / 0.0018);

        // Q = t @ Wq.T + bq   (Wq: [32,3])
        float Qv[32];
        for (int jq = 0; jq < 32; ++jq)
            Qv[jq] = t0 * Wq[jq * 3 + 0] + t1 * Wq[jq * 3 + 1] + t2 * Wq[jq * 3 + 2] + bq[jq];

        float pn[MM][3];
        for (int m = 0; m < MM; ++m) {
            float lys = params[m * 3 + 0];
            pn[m][0] = __fdiv_rn(__fsub_rn(lys, 30.0f), 90.0f);
            pn[m][1] = __fdiv_rn(params[m * 3 + 1], 0.0029f);
            pn[m][2] = __fdiv_rn(params[m * 3 + 2], 0.0018f);
            s_lys[m] = lys;
            s_fac[m] = __fdiv_rn(75.0f, lys);
        }

        // attn[m][h] = (K[m,h,:] . Q[h,:]) / sqrt(8)
        float attn[MM][4];
        for (int m = 0; m < MM; ++m) {
            for (int h = 0; h < 4; ++h) {
                float s = 0.0f;
                for (int d = 0; d < 8; ++d) {
                    int jq = h * 8 + d;
                    float kv = pn[m][0] * Wk[jq * 3 + 0] + pn[m][1] * Wk[jq * 3 + 1]
                             + pn[m][2] * Wk[jq * 3 + 2] + bk[jq];
                    s += kv * Qv[jq];
                }
                attn[m][h] = __fdiv_rn(s, 2.8284271247461903f);
            }
        }

        // softmax over models per head, mean over heads
        float aw[MM];
        for (int m = 0; m < MM; ++m) aw[m] = 0.0f;
        for (int h = 0; h < 4; ++h) {
            float mx = attn[0][h];
            for (int m = 1; m < MM; ++m) mx = fmaxf(mx, attn[m][h]);
            float e[MM], se = 0.0f;
            for (int m = 0; m < MM; ++m) { e[m] = expf(attn[m][h] - mx); se += e[m]; }
            for (int m = 0; m < MM; ++m) aw[m] += __fdiv_rn(e[m], se);
        }
        for (int m = 0; m < MM; ++m) aw[m] *= 0.25f;

        // gaussian similarity weights
        float sw[MM], ssum = 0.0f;
        for (int m = 0; m < MM; ++m) {
            float d0 = __fdiv_rn(__fsub_rn(pn[m][0], t0), 0.25f);
            float d1 = __fdiv_rn(__fsub_rn(pn[m][1], t1), 0.25f);
            float d2 = __fdiv_rn(__fsub_rn(pn[m][2], t2), 0.25f);
            float dist2 = d0 * d0 + d1 * d1 + d2 * d2;
            sw[m] = expf(-dist2 * 0.5f);
            ssum += sw[m];
        }
        float w[MM], wsum = 0.0f;
        for (int m = 0; m < MM; ++m) { w[m] = aw[m] * __fdiv_rn(sw[m], ssum); wsum += w[m]; }
        for (int m = 0; m < MM; ++m) s_w[m] = __fdiv_rn(w[m], wsum);
    }
    __syncthreads();

    // time indices: linspace(0,200,50) -> clip(int(t/200*64),0,63)
    if (tid < NTIMES) {
        float dt = __fdiv_rn(200.0f, 49.0f);
        float tv = (tid == NTIMES - 1) ? 200.0f : __fmul_rn((float)tid, dt);
        float u  = __fmul_rn(__fdiv_rn(tv, 200.0f), 64.0f);
        int idx = (int)u;                // trunc toward zero, values >= 0
        if (idx < 0) idx = 0;
        if (idx > TSOL - 1) idx = TSOL - 1;
        g_tidx[tid] = idx;
    }

    // per (m, j): searchsorted-right on ys_m, fused weights
    const float d01 = __fdiv_rn(1.0f, 255.0f);
    const float dyq = __fdiv_rn(75.0f, 255.0f);
    for (int p = tid; p < MM * NXY; p += blockDim.x) {
        int m = p >> 8, j = p & 255;
        float lys = s_lys[m], fac = s_fac[m], w = s_w[m];
        float yq = (j == NXY - 1) ? 75.0f : __fmul_rn((float)j, dyq);

        // binary search: first k with ys(k) > yq  (side='right')
        int lo = 0, hi = NXY;
        while (lo < hi) {
            int mid = (lo + hi) >> 1;
            if (ys_val(mid, d01, lys, fac) <= yq) lo = mid + 1; else hi = mid;
        }
        int iy = lo - 1;
        if (iy < 0) iy = 0;
        if (iy > NXY - 2) iy = NXY - 2;

        float y0 = ys_val(iy, d01, lys, fac);
        float y1 = ys_val(iy + 1, d01, lys, fac);
        float ty = __fdiv_rn(__fsub_rn(yq, y0), __fsub_rn(y1, y0));

        float ylast = ys_val(NXY - 1, d01, lys, fac);
        bool inb = (yq >= 0.0f) && (yq <= ylast);

        g_iy[p] = iy;
        g_wl[p] = inb ? __fmul_rn(w, __fsub_rn(1.0f, ty)) : 0.0f;
        g_wr[p] = inb ? __fmul_rn(w, ty) : 0.0f;
    }
}

// grid: (i=256, s=2, tgroup=10), block: 256 (j). 5 time-steps per block.
__global__ __launch_bounds__(256) void interp_kernel(const float* __restrict__ c1,
                                                     const float* __restrict__ c2,
                                                     float* __restrict__ out) {
    int j  = threadIdx.x;
    int i  = blockIdx.x;
    int s  = blockIdx.y;
    int tg = blockIdx.z;
    const float* __restrict__ src = s ? c2 : c1;

    float wl[MM], wr[MM];
    int   iy[MM];
#pragma unroll
    for (int m = 0; m < MM; ++m) {
        int p = m * NXY + j;
        wl[m] = g_wl[p];
        wr[m] = g_wr[p];
        iy[m] = g_iy[p];
    }

    bool edge = (s == 0 && j == 0) || (s == 1 && j == NXY - 1);
    float edge_val = (s == 0) ? 0.001f : 0.0001f;

#pragma unroll
    for (int k = 0; k < 5; ++k) {
        int t   = tg * 5 + k;
        int tsl = g_tidx[t];
        float acc = 0.0f;
#pragma unroll
        for (int m = 0; m < MM; ++m) {
            const float* row = src + (((size_t)m * TSOL + tsl) * NXY + i) * NXY;
            float a = __ldg(row + iy[m]);
            float b = __ldg(row + iy[m] + 1);
            acc = fmaf(wl[m], a, acc);
            acc = fmaf(wr[m], b, acc);
        }
        if (edge) acc = edge_val;
        out[(((size_t)s * NTIMES + t) * NXY + i) * NXY + j] = acc;
    }
}

extern "C" void kernel_launch(void* const* d_in, const int* in_sizes, int n_in,
                              void* d_out, int out_size) {
    const float* params = (const float*)d_in[0];
    const float* c1_src = (const float*)d_in[1];
    const float* c2_src = (const float*)d_in[2];
    const float* Wq     = (const float*)d_in[3];
    const float* bq     = (const float*)d_in[4];
    const float* Wk     = (const float*)d_in[5];
    const float* bk     = (const float*)d_in[6];
    float* out = (float*)d_out;

    setup_kernel<<<1, 256>>>(params, Wq, bq, Wk, bk);
    interp_kernel<<<dim3(NXY, 2, 10), 256>>>(c1_src, c2_src, out);
}

// round 3
// speedup vs baseline: 2.3989x; 2.3989x over previous
#include <cuda_runtime.h>
#include <cstdint>
#include <math.h>

#define MM     12     // models
#define TSOL   64
#define NXY    256
#define NTIMES 50

// Scratch (no cudaMalloc allowed)
__device__ float g_wl[MM * NXY];
__device__ float g_wr[MM * NXY];
__device__ int   g_iy[MM * NXY];
__device__ int   g_tidx[NTIMES];

// Replicate jax linspace element: k*fl(delta) for k<n-1, exact stop at k=n-1.
__device__ __forceinline__ float ys_val(int k, float d01, float lys, float fac) {
    float lin = (k == NXY - 1) ? 1.0f : __fmul_rn((float)k, d01);
    return __fmul_rn(__fmul_rn(lin, lys), fac);
}

__global__ void setup_kernel(const float* __restrict__ params,
                             const float* __restrict__ Wq, const float* __restrict__ bq,
                             const float* __restrict__ Wk, const float* __restrict__ bk) {
    __shared__ float s_w[MM], s_lys[MM], s_fac[MM];
    int tid = threadIdx.x;

    if (tid == 0) {
        const float t0 = 0.5f;                       // (75-30)/90
        const float t1 = (float)(0.001 / 0.0029);
        const float t2 = (float)(0.0001 / 0.0018);

        float Qv[32];
        for (int jq = 0; jq < 32; ++jq)
            Qv[jq] = t0 * Wq[jq * 3 + 0] + t1 * Wq[jq * 3 + 1] + t2 * Wq[jq * 3 + 2] + bq[jq];

        float pn[MM][3];
        for (int m = 0; m < MM; ++m) {
            float lys = params[m * 3 + 0];
            pn[m][0] = __fdiv_rn(__fsub_rn(lys, 30.0f), 90.0f);
            pn[m][1] = __fdiv_rn(params[m * 3 + 1], 0.0029f);
            pn[m][2] = __fdiv_rn(params[m * 3 + 2], 0.0018f);
            s_lys[m] = lys;
            s_fac[m] = __fdiv_rn(75.0f, lys);
        }

        float attn[MM][4];
        for (int m = 0; m < MM; ++m) {
            for (int h = 0; h < 4; ++h) {
                float s = 0.0f;
                for (int d = 0; d < 8; ++d) {
                    int jq = h * 8 + d;
                    float kv = pn[m][0] * Wk[jq * 3 + 0] + pn[m][1] * Wk[jq * 3 + 1]
                             + pn[m][2] * Wk[jq * 3 + 2] + bk[jq];
                    s += kv * Qv[jq];
                }
                attn[m][h] = __fdiv_rn(s, 2.8284271247461903f);
            }
        }

        float aw[MM];
        for (int m = 0; m < MM; ++m) aw[m] = 0.0f;
        for (int h = 0; h < 4; ++h) {
            float mx = attn[0][h];
            for (int m = 1; m < MM; ++m) mx = fmaxf(mx, attn[m][h]);
            float e[MM], se = 0.0f;
            for (int m = 0; m < MM; ++m) { e[m] = expf(attn[m][h] - mx); se += e[m]; }
            for (int m = 0; m < MM; ++m) aw[m] += __fdiv_rn(e[m], se);
        }
        for (int m = 0; m < MM; ++m) aw[m] *= 0.25f;

        float sw[MM], ssum = 0.0f;
        for (int m = 0; m < MM; ++m) {
            float d0 = __fdiv_rn(__fsub_rn(pn[m][0], t0), 0.25f);
            float d1 = __fdiv_rn(__fsub_rn(pn[m][1], t1), 0.25f);
            float d2 = __fdiv_rn(__fsub_rn(pn[m][2], t2), 0.25f);
            float dist2 = d0 * d0 + d1 * d1 + d2 * d2;
            sw[m] = expf(-dist2 * 0.5f);
            ssum += sw[m];
        }
        float w[MM], wsum = 0.0f;
        for (int m = 0; m < MM; ++m) { w[m] = aw[m] * __fdiv_rn(sw[m], ssum); wsum += w[m]; }
        for (int m = 0; m < MM; ++m) s_w[m] = __fdiv_rn(w[m], wsum);
    }
    __syncthreads();

    if (tid < NTIMES) {
        float dt = __fdiv_rn(200.0f, 49.0f);
        float tv = (tid == NTIMES - 1) ? 200.0f : __fmul_rn((float)tid, dt);
        float u  = __fmul_rn(__fdiv_rn(tv, 200.0f), 64.0f);
        int idx = (int)u;
        if (idx < 0) idx = 0;
        if (idx > TSOL - 1) idx = TSOL - 1;
        g_tidx[tid] = idx;
    }

    const float d01 = __fdiv_rn(1.0f, 255.0f);
    const float dyq = __fdiv_rn(75.0f, 255.0f);
    for (int p = tid; p < MM * NXY; p += blockDim.x) {
        int m = p >> 8, j = p & 255;
        float lys = s_lys[m], fac = s_fac[m], w = s_w[m];
        float yq = (j == NXY - 1) ? 75.0f : __fmul_rn((float)j, dyq);

        int lo = 0, hi = NXY;
        while (lo < hi) {
            int mid = (lo + hi) >> 1;
            if (ys_val(mid, d01, lys, fac) <= yq) lo = mid + 1; else hi = mid;
        }
        int iy = lo - 1;
        if (iy < 0) iy = 0;
        if (iy > NXY - 2) iy = NXY - 2;

        float y0 = ys_val(iy, d01, lys, fac);
        float y1 = ys_val(iy + 1, d01, lys, fac);
        float ty = __fdiv_rn(__fsub_rn(yq, y0), __fsub_rn(y1, y0));

        float ylast = ys_val(NXY - 1, d01, lys, fac);
        bool inb = (yq >= 0.0f) && (yq <= ylast);

        g_iy[p] = iy;
        g_wl[p] = inb ? __fmul_rn(w, __fsub_rn(1.0f, ty)) : 0.0f;
        g_wr[p] = inb ? __fmul_rn(w, ty) : 0.0f;
    }
}

// ---- main interp: cp.async staged, double-buffered ----

__device__ __forceinline__ void cp_async16(float* smem_dst, const float* gsrc) {
    unsigned int s = (unsigned int)__cvta_generic_to_shared(smem_dst);
    asm volatile("cp.async.cg.shared.global [%0], [%1], 16;\n" :: "r"(s), "l"(gsrc));
}

#define KSTEPS 10

// grid: (i=256, s=2, tg=5), block 256 (j). Each block: 10 time steps, one field.
__global__ __launch_bounds__(256) void interp_kernel(const float* __restrict__ c1,
                                                     const float* __restrict__ c2,
                                                     float* __restrict__ out) {
    __shared__ float sbuf[2][MM][NXY];

    int j  = threadIdx.x;
    int i  = blockIdx.x;
    int s  = blockIdx.y;
    int tg = blockIdx.z;
    const float* __restrict__ src = s ? c2 : c1;

    // weight tables (registers)
    float wl[MM], wr[MM];
    int   iy[MM];
#pragma unroll
    for (int m = 0; m < MM; ++m) {
        int p = m * NXY + j;
        wl[m] = g_wl[p];
        wr[m] = g_wr[p];
        iy[m] = g_iy[p];
    }

    // cooperative load assignment: 3 rounds x (row = r*4 + j/64, 16B @ (j%64)*16)
    const int lrow = j >> 6;          // 0..3
    const int loff = (j & 63) << 2;   // float offset of this thread's 16B chunk
    const int T0 = tg * KSTEPS;

    // prefetch step 0
    {
        int tsl = g_tidx[T0];
#pragma unroll
        for (int r = 0; r < 3; ++r) {
            int m = r * 4 + lrow;
            const float* gp = src + (((size_t)m * TSOL + tsl) * NXY + i) * NXY + loff;
            cp_async16(&sbuf[0][m][loff], gp);
        }
        asm volatile("cp.async.commit_group;\n");
    }

    bool edge = (s == 0 && j == 0) || (s == 1 && j == NXY - 1);
    float edge_val = (s == 0) ? 0.001f : 0.0001f;

#pragma unroll
    for (int k = 0; k < KSTEPS; ++k) {
        int buf = k & 1;
        if (k < KSTEPS - 1) {
            int tsl = g_tidx[T0 + k + 1];
#pragma unroll
            for (int r = 0; r < 3; ++r) {
                int m = r * 4 + lrow;
                const float* gp = src + (((size_t)m * TSOL + tsl) * NXY + i) * NXY + loff;
                cp_async16(&sbuf[buf ^ 1][m][loff], gp);
            }
            asm volatile("cp.async.commit_group;\n");
            asm volatile("cp.async.wait_group 1;\n");
        } else {
            asm volatile("cp.async.wait_group 0;\n");
        }
        __syncthreads();

        float acc = 0.0f;
#pragma unroll
        for (int m = 0; m < MM; ++m) {
            float a = sbuf[buf][m][iy[m]];
            float b = sbuf[buf][m][iy[m] + 1];
            acc = fmaf(wl[m], a, acc);
            acc = fmaf(wr[m], b, acc);
        }
        if (edge) acc = edge_val;
        out[(((size_t)s * NTIMES + T0 + k) * NXY + i) * NXY + j] = acc;

        __syncthreads();   // protect buf^1 before it is overwritten next iter
    }
}

extern "C" void kernel_launch(void* const* d_in, const int* in_sizes, int n_in,
                              void* d_out, int out_size) {
    const float* params = (const float*)d_in[0];
    const float* c1_src = (const float*)d_in[1];
    const float* c2_src = (const float*)d_in[2];
    const float* Wq     = (const float*)d_in[3];
    const float* bq     = (const float*)d_in[4];
    const float* Wk     = (const float*)d_in[5];
    const float* bk     = (const float*)d_in[6];
    float* out = (float*)d_out;

    setup_kernel<<<1, 256>>>(params, Wq, bq, Wk, bk);
    interp_kernel<<<dim3(NXY, 2, 5), 256>>>(c1_src, c2_src, out);
}